// round 10
// baseline (speedup 1.0000x reference)
#include <cuda_runtime.h>

// GridMask: out = x * mask(n,s,h,w), broadcast over C.
// x: [N=8, C=3, S=16, H=512, W=512] fp32
// d: [N] int32, st_h/st_w: [N, S] int32
// mask = ((h + OFF_H - st_h) mod d < l) || ((w + OFF_W - st_w) mod d < l),
// l = ceil(d/2), OFF_H = OFF_W = 106.
//
// R8 variant: 2 rows per CTA, 2 col-groups per thread.
//  - 128 threads: tsub = tid&63 -> col-groups at w=tsub*4 and w=tsub*4+256,
//    row = h0 + (tid>>6). Each warp stays contiguous (512B per LDG).
//  - per-thread MLP 3 -> 6 independent LDG.128 (better latency hiding),
//    32768 blocks instead of 65536.
//  - mask==0 col-groups skip the x read (independent predicate per group).

#define GN 8
#define GC 3
#define GS 16
#define GH 512
#define GW 512
#define OFF_H 106
#define OFF_W 106

__global__ __launch_bounds__(128, 16)
void gridmask_kernel(const float* __restrict__ x,
                     const int* __restrict__ d,
                     const int* __restrict__ st_h,
                     const int* __restrict__ st_w,
                     float* __restrict__ out) {
    // blockIdx.x encodes (n, s, hpair): bid = ((n*GS + s) << 8) | (h >> 1)
    const int bid = blockIdx.x;
    const int hp = bid & 255;                     // h pair index
    const int ns = bid >> 8;
    const int s  = ns & (GS - 1);
    const int n  = ns >> 4;

    const int tid  = threadIdx.x;
    const int tsub = tid & 63;
    const int h    = (hp << 1) | (tid >> 6);      // this thread's row

    const int dn = d[n];
    const int l  = (dn + 1) >> 1;                 // ceil(d * 0.5)
    const int sh = st_h[n * GS + s] % dn;
    const int sw = st_w[n * GS + s] % dn;

    const unsigned ud = (unsigned)dn;
    const unsigned ul = (unsigned)l;

    // h + OFF_H - sh + dn >= 107 > 0 -> single unsigned mod ok
    const bool row_hit =
        ((unsigned)(h + OFF_H - sh + dn) % ud) < ul;

    // Two col-groups per thread: w0 = tsub*4, w1 = w0 + 256.
    const int w0 = tsub << 2;
    const int w1 = w0 + 256;

    // col hits for both groups (single mod each; lane offsets via wrap, <d)
    unsigned a0 = (unsigned)(w0 + OFF_W - sw + dn) % ud;
    unsigned a1 = a0 + 1u; if (a1 >= ud) a1 -= ud;
    unsigned a2 = a0 + 2u; if (a2 >= ud) a2 -= ud;
    unsigned a3 = a0 + 3u; if (a3 >= ud) a3 -= ud;
    unsigned b0 = (unsigned)(w1 + OFF_W - sw + dn) % ud;
    unsigned b1 = b0 + 1u; if (b1 >= ud) b1 -= ud;
    unsigned b2 = b0 + 2u; if (b2 >= ud) b2 -= ud;
    unsigned b3 = b0 + 3u; if (b3 >= ud) b3 -= ud;

    const bool ca0 = a0 < ul, ca1 = a1 < ul, ca2 = a2 < ul, ca3 = a3 < ul;
    const bool cb0 = b0 < ul, cb1 = b1 < ul, cb2 = b2 < ul, cb3 = b3 < ul;

    const bool anyA = row_hit | ca0 | ca1 | ca2 | ca3;
    const bool anyB = row_hit | cb0 | cb1 | cb2 | cb3;

    // layout: idx = (((n*C + c)*S + s)*H + h)*W + w ; channel stride = S*H*W
    const size_t cstride = (size_t)GS * GH * GW;  // 4194304
    const size_t rowbase = (((size_t)n * GC) * GS + (size_t)s) * ((size_t)GH * GW)
                         + (size_t)h * GW;
    const size_t baseA = rowbase + (size_t)w0;
    const size_t baseB = rowbase + (size_t)w1;

    float4 vA0 = make_float4(0.f, 0.f, 0.f, 0.f), vA1 = vA0, vA2 = vA0;
    float4 vB0 = vA0, vB1 = vA0, vB2 = vA0;

    if (anyA) {
        vA0 = __ldcs(reinterpret_cast<const float4*>(x + baseA));
        vA1 = __ldcs(reinterpret_cast<const float4*>(x + baseA + cstride));
        vA2 = __ldcs(reinterpret_cast<const float4*>(x + baseA + 2 * cstride));
    }
    if (anyB) {
        vB0 = __ldcs(reinterpret_cast<const float4*>(x + baseB));
        vB1 = __ldcs(reinterpret_cast<const float4*>(x + baseB + cstride));
        vB2 = __ldcs(reinterpret_cast<const float4*>(x + baseB + 2 * cstride));
    }

    if (anyA) {
        const float m0 = (row_hit | ca0) ? 1.0f : 0.0f;
        const float m1 = (row_hit | ca1) ? 1.0f : 0.0f;
        const float m2 = (row_hit | ca2) ? 1.0f : 0.0f;
        const float m3 = (row_hit | ca3) ? 1.0f : 0.0f;
        vA0.x *= m0; vA0.y *= m1; vA0.z *= m2; vA0.w *= m3;
        vA1.x *= m0; vA1.y *= m1; vA1.z *= m2; vA1.w *= m3;
        vA2.x *= m0; vA2.y *= m1; vA2.z *= m2; vA2.w *= m3;
    }
    if (anyB) {
        const float m0 = (row_hit | cb0) ? 1.0f : 0.0f;
        const float m1 = (row_hit | cb1) ? 1.0f : 0.0f;
        const float m2 = (row_hit | cb2) ? 1.0f : 0.0f;
        const float m3 = (row_hit | cb3) ? 1.0f : 0.0f;
        vB0.x *= m0; vB0.y *= m1; vB0.z *= m2; vB0.w *= m3;
        vB1.x *= m0; vB1.y *= m1; vB1.z *= m2; vB1.w *= m3;
        vB2.x *= m0; vB2.y *= m1; vB2.z *= m2; vB2.w *= m3;
    }

    __stcs(reinterpret_cast<float4*>(out + baseA),                vA0);
    __stcs(reinterpret_cast<float4*>(out + baseA + cstride),      vA1);
    __stcs(reinterpret_cast<float4*>(out + baseA + 2 * cstride),  vA2);
    __stcs(reinterpret_cast<float4*>(out + baseB),                vB0);
    __stcs(reinterpret_cast<float4*>(out + baseB + cstride),      vB1);
    __stcs(reinterpret_cast<float4*>(out + baseB + 2 * cstride),  vB2);
}

extern "C" void kernel_launch(void* const* d_in, const int* in_sizes, int n_in,
                              void* d_out, int out_size) {
    const float* x   = (const float*)d_in[0];
    const int* d     = (const int*)d_in[1];
    const int* st_h  = (const int*)d_in[2];
    const int* st_w  = (const int*)d_in[3];
    float* out       = (float*)d_out;

    // one block per (n, s, h-pair): 8*16*256 = 32768 blocks, 128 threads each
    gridmask_kernel<<<GN * GS * (GH / 2), 128>>>(x, d, st_h, st_w, out);
}

// round 11
// speedup vs baseline: 1.0378x; 1.0378x over previous
#include <cuda_runtime.h>

// GridMask: out = x * mask(n,s,h,w), broadcast over C.
// x: [N=8, C=3, S=16, H=512, W=512] fp32
// d: [N] int32, st_h/st_w: [N, S] int32
// mask = ((h + OFF_H - st_h) mod d < l) || ((w + OFF_W - st_w) mod d < l),
// l = ceil(d/2), OFF_H = OFF_W = 106 (HH = ceil(512*sqrt(2)) = 725).
//
// FINAL (Round-4 winner, roofline-complete at ~700MB of mandatory traffic):
//  - one CTA per (n,s,h) row, 128 threads x float4, fully coalesced
//  - mask==0 spans skip the x read entirely (~24% of read traffic removed;
//    zero runs are 192-448B >> 32B sectors, so predicated LDGs drop sectors)
//  - straight-line body, 16 CTAs/SM resident: CTA-level parallelism supplies
//    the memory-level parallelism. Measured alternatives all worse/neutral:
//    persistent grid-stride loop (+18%), MLP=6/thread 2-row variant (+4%),
//    streaming-hint-only and ALU-trimming variants (neutral).

#define GN 8
#define GC 3
#define GS 16
#define GH 512
#define GW 512
#define OFF_H 106
#define OFF_W 106

__global__ __launch_bounds__(128, 16)
void gridmask_kernel(const float* __restrict__ x,
                     const int* __restrict__ d,
                     const int* __restrict__ st_h,
                     const int* __restrict__ st_w,
                     float* __restrict__ out) {
    // blockIdx.x encodes (n, s, h): bid = ((n*GS + s) << 9) | h
    const int bid = blockIdx.x;
    const int h  = bid & (GH - 1);
    const int ns = bid >> 9;
    const int s  = ns & (GS - 1);
    const int n  = ns >> 4;

    const int dn = d[n];
    const int l  = (dn + 1) >> 1;                 // ceil(d * 0.5)
    const int sh = st_h[n * GS + s] % dn;
    const int sw = st_w[n * GS + s] % dn;

    // h + OFF_H - sh + dn >= 107 > 0  -> single unsigned mod ok
    const bool row_hit =
        ((unsigned)(h + OFF_H - sh + dn) % (unsigned)dn) < (unsigned)l;

    const int w = threadIdx.x << 2;               // 0,4,...,508

    // per-lane column hits
    const unsigned ud = (unsigned)dn;
    const unsigned ul = (unsigned)l;
    const unsigned cb = (unsigned)(w + OFF_W - sw + dn);
    const bool c0 = ((cb + 0u) % ud) < ul;
    const bool c1 = ((cb + 1u) % ud) < ul;
    const bool c2 = ((cb + 2u) % ud) < ul;
    const bool c3 = ((cb + 3u) % ud) < ul;

    const bool any = row_hit | c0 | c1 | c2 | c3;

    const float m0 = (row_hit | c0) ? 1.0f : 0.0f;
    const float m1 = (row_hit | c1) ? 1.0f : 0.0f;
    const float m2 = (row_hit | c2) ? 1.0f : 0.0f;
    const float m3 = (row_hit | c3) ? 1.0f : 0.0f;

    // layout: idx = (((n*C + c)*S + s)*H + h)*W + w ; channel stride = S*H*W
    const size_t cstride = (size_t)GS * GH * GW;  // 4194304
    const size_t base0 = (((size_t)n * GC) * GS + (size_t)s) * ((size_t)GH * GW)
                       + (size_t)h * GW + (size_t)w;

    const float4* p0 = reinterpret_cast<const float4*>(x + base0);
    const float4* p1 = reinterpret_cast<const float4*>(x + base0 + cstride);
    const float4* p2 = reinterpret_cast<const float4*>(x + base0 + 2 * cstride);

    float4 v0 = make_float4(0.f, 0.f, 0.f, 0.f);
    float4 v1 = v0;
    float4 v2 = v0;

    // Skip the reads entirely when all 4 mask lanes are zero (output is 0).
    if (any) {
        v0 = __ldcs(p0);
        v1 = __ldcs(p1);
        v2 = __ldcs(p2);

        v0.x *= m0; v0.y *= m1; v0.z *= m2; v0.w *= m3;
        v1.x *= m0; v1.y *= m1; v1.z *= m2; v1.w *= m3;
        v2.x *= m0; v2.y *= m1; v2.z *= m2; v2.w *= m3;
    }

    __stcs(reinterpret_cast<float4*>(out + base0),                v0);
    __stcs(reinterpret_cast<float4*>(out + base0 + cstride),      v1);
    __stcs(reinterpret_cast<float4*>(out + base0 + 2 * cstride),  v2);
}

extern "C" void kernel_launch(void* const* d_in, const int* in_sizes, int n_in,
                              void* d_out, int out_size) {
    const float* x   = (const float*)d_in[0];
    const int* d     = (const int*)d_in[1];
    const int* st_h  = (const int*)d_in[2];
    const int* st_w  = (const int*)d_in[3];
    float* out       = (float*)d_out;

    // one block per (n, s, h) row: 8*16*512 = 65536 blocks, 128 threads each
    gridmask_kernel<<<GN * GS * GH, 128>>>(x, d, st_h, st_w, out);
}

// round 12
// speedup vs baseline: 1.0381x; 1.0003x over previous
#include <cuda_runtime.h>

// GridMask: out = x * mask(n,s,h,w), broadcast over C.
// x: [N=8, C=3, S=16, H=512, W=512] fp32
// d: [N] int32, st_h/st_w: [N, S] int32
// mask = ((h + OFF_H - st_h) mod d < l) || ((w + OFF_W - st_w) mod d < l),
// l = ceil(d/2), OFF_H = OFF_W = 106 (HH = ceil(512*sqrt(2)) = 725).
//
// FINAL — roofline-complete at ~700MB of mandatory traffic (measured 694MB
// @ 6.4TB/s; 4x reproduced at 116.5-116.8us total):
//  - one CTA per (n,s,h) row, 128 threads x float4, fully coalesced
//  - mask==0 spans skip the x read entirely (~24% of read traffic removed;
//    zero runs are 192-448B >> 32B sectors, so predicated LDGs drop sectors)
//  - straight-line body, 16 CTAs/SM resident: CTA-level parallelism supplies
//    the memory-level parallelism. Measured alternatives all worse/neutral:
//    persistent grid-stride loop (+18%), MLP=6/thread 2-row variant (+4%),
//    streaming-hint-only and ALU-trimming variants (neutral).

#define GN 8
#define GC 3
#define GS 16
#define GH 512
#define GW 512
#define OFF_H 106
#define OFF_W 106

__global__ __launch_bounds__(128, 16)
void gridmask_kernel(const float* __restrict__ x,
                     const int* __restrict__ d,
                     const int* __restrict__ st_h,
                     const int* __restrict__ st_w,
                     float* __restrict__ out) {
    // blockIdx.x encodes (n, s, h): bid = ((n*GS + s) << 9) | h
    const int bid = blockIdx.x;
    const int h  = bid & (GH - 1);
    const int ns = bid >> 9;
    const int s  = ns & (GS - 1);
    const int n  = ns >> 4;

    const int dn = d[n];
    const int l  = (dn + 1) >> 1;                 // ceil(d * 0.5)
    const int sh = st_h[n * GS + s] % dn;
    const int sw = st_w[n * GS + s] % dn;

    // h + OFF_H - sh + dn >= 107 > 0  -> single unsigned mod ok
    const bool row_hit =
        ((unsigned)(h + OFF_H - sh + dn) % (unsigned)dn) < (unsigned)l;

    const int w = threadIdx.x << 2;               // 0,4,...,508

    // per-lane column hits
    const unsigned ud = (unsigned)dn;
    const unsigned ul = (unsigned)l;
    const unsigned cb = (unsigned)(w + OFF_W - sw + dn);
    const bool c0 = ((cb + 0u) % ud) < ul;
    const bool c1 = ((cb + 1u) % ud) < ul;
    const bool c2 = ((cb + 2u) % ud) < ul;
    const bool c3 = ((cb + 3u) % ud) < ul;

    const bool any = row_hit | c0 | c1 | c2 | c3;

    const float m0 = (row_hit | c0) ? 1.0f : 0.0f;
    const float m1 = (row_hit | c1) ? 1.0f : 0.0f;
    const float m2 = (row_hit | c2) ? 1.0f : 0.0f;
    const float m3 = (row_hit | c3) ? 1.0f : 0.0f;

    // layout: idx = (((n*C + c)*S + s)*H + h)*W + w ; channel stride = S*H*W
    const size_t cstride = (size_t)GS * GH * GW;  // 4194304
    const size_t base0 = (((size_t)n * GC) * GS + (size_t)s) * ((size_t)GH * GW)
                       + (size_t)h * GW + (size_t)w;

    const float4* p0 = reinterpret_cast<const float4*>(x + base0);
    const float4* p1 = reinterpret_cast<const float4*>(x + base0 + cstride);
    const float4* p2 = reinterpret_cast<const float4*>(x + base0 + 2 * cstride);

    float4 v0 = make_float4(0.f, 0.f, 0.f, 0.f);
    float4 v1 = v0;
    float4 v2 = v0;

    // Skip the reads entirely when all 4 mask lanes are zero (output is 0).
    if (any) {
        v0 = __ldcs(p0);
        v1 = __ldcs(p1);
        v2 = __ldcs(p2);

        v0.x *= m0; v0.y *= m1; v0.z *= m2; v0.w *= m3;
        v1.x *= m0; v1.y *= m1; v1.z *= m2; v1.w *= m3;
        v2.x *= m0; v2.y *= m1; v2.z *= m2; v2.w *= m3;
    }

    __stcs(reinterpret_cast<float4*>(out + base0),                v0);
    __stcs(reinterpret_cast<float4*>(out + base0 + cstride),      v1);
    __stcs(reinterpret_cast<float4*>(out + base0 + 2 * cstride),  v2);
}

extern "C" void kernel_launch(void* const* d_in, const int* in_sizes, int n_in,
                              void* d_out, int out_size) {
    const float* x   = (const float*)d_in[0];
    const int* d     = (const int*)d_in[1];
    const int* st_h  = (const int*)d_in[2];
    const int* st_w  = (const int*)d_in[3];
    float* out       = (float*)d_out;

    // one block per (n, s, h) row: 8*16*512 = 65536 blocks, 128 threads each
    gridmask_kernel<<<GN * GS * GH, 128>>>(x, d, st_h, st_w, out);
}